// round 9
// baseline (speedup 1.0000x reference)
#include <cuda_runtime.h>
#include <math.h>

#define Bc 4
#define Sc 2048
#define Ec 1024
#define Hc 16
#define Mc 256
#define Dc 64

typedef unsigned long long u64;

// ---------------- packed f32x2 helpers (Blackwell FFMA2) ----------------
__device__ __forceinline__ u64 ffma2(u64 a, u64 b, u64 c) {
    u64 d;
    asm("fma.rn.f32x2 %0, %1, %2, %3;" : "=l"(d) : "l"(a), "l"(b), "l"(c));
    return d;
}
__device__ __forceinline__ u64 pack2(float x, float y) {
    u64 r;
    asm("mov.b64 %0, {%1, %2};" : "=l"(r) : "f"(x), "f"(y));
    return r;
}
__device__ __forceinline__ float2 unpack2(u64 v) {
    float2 r;
    asm("mov.b64 {%0, %1}, %2;" : "=f"(r.x), "=f"(r.y) : "l"(v));
    return r;
}

// ---------------- scratch (device globals; no runtime allocation) ----------------
__device__ float g_Q[Bc*Sc*Ec];
__device__ float g_K[Bc*Sc*Ec];
__device__ float g_V[Bc*Sc*Ec];
__device__ float g_qp[(size_t)Bc*Hc*Sc*Mc];
__device__ float g_kp[(size_t)Bc*Hc*Sc*Mc];
__device__ float g_attn[Bc*Sc*Ec];
__device__ float g_res[Bc*Sc*Ec];

// ---------------- fp32 tiled GEMM (FFMA2 core, reg-staged double buffer) ----------------
// C = A@B + bias (+ add). A:[Mr,K] B:[K,N] bias:[N] add:[Mr,N]|null C:[Mr,N]
// BM=BN=128, BK=16, 256 threads, 8x8 per thread (as 8x4 f32x2 pairs).
__global__ void __launch_bounds__(256)
sgemm_bias(const float* __restrict__ A, const float* __restrict__ B,
           const float* __restrict__ bias, const float* __restrict__ add,
           float* __restrict__ C, int Mr, int N, int K)
{
    __shared__ __align__(16) float As[16][128];
    __shared__ __align__(16) float Bs[16][128];
    const int tid  = threadIdx.x;
    const int tx   = tid & 15;
    const int ty   = tid >> 4;
    const int row0 = blockIdx.y * 128;
    const int col0 = blockIdx.x * 128;

    const int id0 = tid << 1;
    int rA[2], kcA[2], krB[2], ncB[2];
    #pragma unroll
    for (int i = 0; i < 2; i++) {
        const int id = id0 + i;
        rA[i]  = id >> 2;
        kcA[i] = (id & 3) << 2;
        krB[i] = id >> 5;
        ncB[i] = (id & 31) << 2;
    }

    float4 pa[2], pb[2];
    #pragma unroll
    for (int i = 0; i < 2; i++) {
        pa[i] = *(const float4*)(A + (size_t)(row0 + rA[i]) * K + kcA[i]);
        pb[i] = *(const float4*)(B + (size_t)krB[i] * N + col0 + ncB[i]);
    }
    #pragma unroll
    for (int i = 0; i < 2; i++) {
        As[kcA[i] + 0][rA[i]] = pa[i].x;
        As[kcA[i] + 1][rA[i]] = pa[i].y;
        As[kcA[i] + 2][rA[i]] = pa[i].z;
        As[kcA[i] + 3][rA[i]] = pa[i].w;
        *(float4*)(&Bs[krB[i]][ncB[i]]) = pb[i];
    }
    __syncthreads();

    u64 acc[8][4];
    #pragma unroll
    for (int i = 0; i < 8; i++)
        #pragma unroll
        for (int j = 0; j < 4; j++) acc[i][j] = 0ull;

    const int nT = K >> 4;
    for (int t = 0; t < nT; t++) {
        const int k0n = (t + 1) << 4;
        if (k0n < K) {
            #pragma unroll
            for (int i = 0; i < 2; i++) {
                pa[i] = *(const float4*)(A + (size_t)(row0 + rA[i]) * K + k0n + kcA[i]);
                pb[i] = *(const float4*)(B + (size_t)(k0n + krB[i]) * N + col0 + ncB[i]);
            }
        }
        #pragma unroll
        for (int k = 0; k < 16; k++) {
            float4 a0 = *(const float4*)(&As[k][ty * 8]);
            float4 a1 = *(const float4*)(&As[k][ty * 8 + 4]);
            ulonglong2 b0 = *(const ulonglong2*)(&Bs[k][tx * 8]);
            ulonglong2 b1 = *(const ulonglong2*)(&Bs[k][tx * 8 + 4]);
            u64 rb[4] = { b0.x, b0.y, b1.x, b1.y };
            u64 ra[8] = { pack2(a0.x, a0.x), pack2(a0.y, a0.y),
                          pack2(a0.z, a0.z), pack2(a0.w, a0.w),
                          pack2(a1.x, a1.x), pack2(a1.y, a1.y),
                          pack2(a1.z, a1.z), pack2(a1.w, a1.w) };
            #pragma unroll
            for (int i = 0; i < 8; i++)
                #pragma unroll
                for (int j = 0; j < 4; j++)
                    acc[i][j] = ffma2(ra[i], rb[j], acc[i][j]);
        }
        __syncthreads();
        if (k0n < K) {
            #pragma unroll
            for (int i = 0; i < 2; i++) {
                As[kcA[i] + 0][rA[i]] = pa[i].x;
                As[kcA[i] + 1][rA[i]] = pa[i].y;
                As[kcA[i] + 2][rA[i]] = pa[i].z;
                As[kcA[i] + 3][rA[i]] = pa[i].w;
                *(float4*)(&Bs[krB[i]][ncB[i]]) = pb[i];
            }
            __syncthreads();
        }
    }

    #pragma unroll
    for (int i = 0; i < 8; i++) {
        const size_t rbase = (size_t)(row0 + ty * 8 + i) * N;
        const int ci = col0 + tx * 8;
        const float2 v0 = unpack2(acc[i][0]);
        const float2 v1 = unpack2(acc[i][1]);
        const float2 v2 = unpack2(acc[i][2]);
        const float2 v3 = unpack2(acc[i][3]);
        float4 r0, r1;
        r0.x = v0.x + __ldg(bias + ci + 0);
        r0.y = v0.y + __ldg(bias + ci + 1);
        r0.z = v1.x + __ldg(bias + ci + 2);
        r0.w = v1.y + __ldg(bias + ci + 3);
        r1.x = v2.x + __ldg(bias + ci + 4);
        r1.y = v2.y + __ldg(bias + ci + 5);
        r1.z = v3.x + __ldg(bias + ci + 6);
        r1.w = v3.y + __ldg(bias + ci + 7);
        if (add) {
            const float4 a0 = *(const float4*)(add + rbase + ci);
            const float4 a1 = *(const float4*)(add + rbase + ci + 4);
            r0.x += a0.x; r0.y += a0.y; r0.z += a0.z; r0.w += a0.w;
            r1.x += a1.x; r1.y += a1.y; r1.z += a1.z; r1.w += a1.w;
        }
        *(float4*)(C + rbase + ci)     = r0;
        *(float4*)(C + rbase + ci + 4) = r1;
    }
}

// ---------------- feature map (FFMA2) ----------------
__global__ void __launch_bounds__(256)
feature_kernel(const float* __restrict__ A, const float* __restrict__ proj,
               float* __restrict__ out)
{
    __shared__ __align__(16) float As[16][128];
    __shared__ __align__(16) float Bs[16][128];
    __shared__ float s2[128][2];
    const int tid  = threadIdx.x;
    const int tx   = tid & 15;
    const int ty   = tid >> 4;
    const int row0 = blockIdx.y * 128;
    const int col0 = blockIdx.x * 128;

    {
        int r = tid >> 1, half = tid & 1;
        const float* p = A + (size_t)(row0 + r) * Dc + half * 32;
        float s = 0.f;
        #pragma unroll
        for (int i = 0; i < 32; i++) s = fmaf(p[i], p[i], s);
        s2[r][half] = s;
    }

    u64 acc[8][4];
    #pragma unroll
    for (int i = 0; i < 8; i++)
        #pragma unroll
        for (int j = 0; j < 4; j++) acc[i][j] = 0ull;

    for (int k0 = 0; k0 < Dc; k0 += 16) {
        #pragma unroll
        for (int i = 0; i < 2; i++) {
            int id = (tid << 1) + i;
            int r  = id >> 2;
            int kc = (id & 3) << 2;
            const float4 a = *(const float4*)(A + (size_t)(row0 + r) * Dc + k0 + kc);
            As[kc + 0][r] = a.x;
            As[kc + 1][r] = a.y;
            As[kc + 2][r] = a.z;
            As[kc + 3][r] = a.w;
            int kr = id >> 5;
            int nc = (id & 31) << 2;
            Bs[kr][nc + 0] = proj[(size_t)(col0 + nc + 0) * Dc + k0 + kr];
            Bs[kr][nc + 1] = proj[(size_t)(col0 + nc + 1) * Dc + k0 + kr];
            Bs[kr][nc + 2] = proj[(size_t)(col0 + nc + 2) * Dc + k0 + kr];
            Bs[kr][nc + 3] = proj[(size_t)(col0 + nc + 3) * Dc + k0 + kr];
        }
        __syncthreads();
        #pragma unroll
        for (int k = 0; k < 16; k++) {
            float4 a0 = *(const float4*)(&As[k][ty * 8]);
            float4 a1 = *(const float4*)(&As[k][ty * 8 + 4]);
            ulonglong2 b0 = *(const ulonglong2*)(&Bs[k][tx * 8]);
            ulonglong2 b1 = *(const ulonglong2*)(&Bs[k][tx * 8 + 4]);
            u64 rb[4] = { b0.x, b0.y, b1.x, b1.y };
            u64 ra[8] = { pack2(a0.x, a0.x), pack2(a0.y, a0.y),
                          pack2(a0.z, a0.z), pack2(a0.w, a0.w),
                          pack2(a1.x, a1.x), pack2(a1.y, a1.y),
                          pack2(a1.z, a1.z), pack2(a1.w, a1.w) };
            #pragma unroll
            for (int i = 0; i < 8; i++)
                #pragma unroll
                for (int j = 0; j < 4; j++)
                    acc[i][j] = ffma2(ra[i], rb[j], acc[i][j]);
        }
        __syncthreads();
    }

    #pragma unroll
    for (int i = 0; i < 8; i++) {
        const int rr = ty * 8 + i;
        const int r  = row0 + rr;
        const float ss = s2[rr][0] + s2[rr][1];
        const int b = r >> 15;
        const int s = (r >> 4) & (Sc - 1);
        const int h = r & (Hc - 1);
        const size_t obase = ((size_t)(b * Hc + h) * Sc + s) * Mc + col0 + tx * 8;
        const float corr = ss * (1.f / 128.f);
        float vals[8];
        const float2 v0 = unpack2(acc[i][0]);
        const float2 v1 = unpack2(acc[i][1]);
        const float2 v2 = unpack2(acc[i][2]);
        const float2 v3 = unpack2(acc[i][3]);
        vals[0] = v0.x; vals[1] = v0.y; vals[2] = v1.x; vals[3] = v1.y;
        vals[4] = v2.x; vals[5] = v2.y; vals[6] = v3.x; vals[7] = v3.y;
        #pragma unroll
        for (int j = 0; j < 8; j++)
            out[obase + j] = 0.0625f * expf(fmaf(vals[j], 0.125f, -corr));
    }
}

// ---------------- causal linear-attention scan, D split across 2 CTAs ----------------
// CTA = (bh, half). Thread (c=tid>>5, dl=tid&31) owns kv[m in c*32..c*32+31][half*32+dl].
// 128 CTAs -> ~1 per SM (vs 64 before): compute floor halves.
__global__ void __launch_bounds__(256)
scan_kernel(const float* __restrict__ qp, const float* __restrict__ kp,
            const float* __restrict__ V, float* __restrict__ attn)
{
    const int bh   = blockIdx.x >> 1;
    const int half = blockIdx.x & 1;
    const int b    = bh >> 4;
    const int h    = bh & 15;
    const int tid  = threadIdx.x;
    const int c    = tid >> 5;    // 0..7 (m-chunk)
    const int dl   = tid & 31;    // 0..31 (local d)

    __shared__ __align__(16) float q_sh[256];
    __shared__ __align__(16) float k_sh[256];
    __shared__ float v_sh[32];
    __shared__ float ksum_sh[256];
    __shared__ float nred[8][32];
    __shared__ float dred[8];

    u64 kv[16];
    #pragma unroll
    for (int i = 0; i < 16; i++) kv[i] = 0ull;
    ksum_sh[tid] = 0.f;

    const float* qpb = qp + (size_t)bh * Sc * Mc;
    const float* kpb = kp + (size_t)bh * Sc * Mc;
    const float* Vb  = V + ((size_t)b * Sc * Hc + h) * Dc + half * 32;
    float*       ab  = attn + ((size_t)b * Sc * Hc + h) * Dc + half * 32;

    // prefetch step 0
    float qn = qpb[tid];
    float kn = kpb[tid];
    float vn = (tid < 32) ? Vb[tid] : 0.f;

    for (int s = 0; s < Sc; s++) {
        q_sh[tid] = qn;
        k_sh[tid] = kn;
        if (tid < 32) v_sh[tid] = vn;
        __syncthreads();

        // prefetch next step (hidden under compute)
        if (s + 1 < Sc) {
            qn = qpb[(size_t)(s + 1) * Mc + tid];
            kn = kpb[(size_t)(s + 1) * Mc + tid];
            if (tid < 32) vn = Vb[(size_t)(s + 1) * Hc * Dc + tid];
        }

        // ksum update + den partial (thread t owns m = t; warp w covers m in [32w,32w+32))
        float ks = ksum_sh[tid] + k_sh[tid];
        ksum_sh[tid] = ks;
        float dp = q_sh[tid] * ks;
        #pragma unroll
        for (int o = 16; o > 0; o >>= 1) dp += __shfl_down_sync(0xffffffffu, dp, o);
        if (dl == 0) dred[c] = dp;

        // kv update + num partial over this thread's 32 m-values (f32x2)
        const u64 vd2 = pack2(v_sh[dl], v_sh[dl]);
        u64 np0 = 0ull, np1 = 0ull;
        const ulonglong2* k4 = (const ulonglong2*)(k_sh + (c << 5));
        const ulonglong2* q4 = (const ulonglong2*)(q_sh + (c << 5));
        #pragma unroll
        for (int i = 0; i < 8; i++) {
            const ulonglong2 kk = k4[i];
            const ulonglong2 qq = q4[i];
            kv[2*i + 0] = ffma2(kk.x, vd2, kv[2*i + 0]);
            np0 = ffma2(kv[2*i + 0], qq.x, np0);
            kv[2*i + 1] = ffma2(kk.y, vd2, kv[2*i + 1]);
            np1 = ffma2(kv[2*i + 1], qq.y, np1);
        }
        const float2 n0 = unpack2(np0);
        const float2 n1 = unpack2(np1);
        nred[c][dl] = (n0.x + n0.y) + (n1.x + n1.y);
        __syncthreads();

        if (tid < 32) {
            const float num = nred[0][tid] + nred[1][tid] + nred[2][tid] + nred[3][tid]
                            + nred[4][tid] + nred[5][tid] + nred[6][tid] + nred[7][tid];
            const float den = dred[0] + dred[1] + dred[2] + dred[3]
                            + dred[4] + dred[5] + dred[6] + dred[7];
            ab[(size_t)s * Hc * Dc + tid] = num / den;
        }
    }
}

// ---------------- layernorm ----------------
__global__ void __launch_bounds__(256)
ln_kernel(const float* __restrict__ res, const float* __restrict__ gamma,
          const float* __restrict__ beta, float* __restrict__ out)
{
    const int row = blockIdx.x;
    const int tid = threadIdx.x;
    const float4 v = *(const float4*)(res + (size_t)row * Ec + tid * 4);
    float s  = v.x + v.y + v.z + v.w;
    float sq = v.x * v.x + v.y * v.y + v.z * v.z + v.w * v.w;
    #pragma unroll
    for (int o = 16; o > 0; o >>= 1) {
        s  += __shfl_down_sync(0xffffffffu, s,  o);
        sq += __shfl_down_sync(0xffffffffu, sq, o);
    }
    __shared__ float ssh[8], sqsh[8];
    __shared__ float s_mu, s_rs;
    if ((tid & 31) == 0) { ssh[tid >> 5] = s; sqsh[tid >> 5] = sq; }
    __syncthreads();
    if (tid == 0) {
        float S = 0.f, Q = 0.f;
        #pragma unroll
        for (int w = 0; w < 8; w++) { S += ssh[w]; Q += sqsh[w]; }
        const float mu  = S * (1.f / Ec);
        const float var = Q * (1.f / Ec) - mu * mu;
        s_mu = mu;
        s_rs = rsqrtf(var + 1e-6f);
    }
    __syncthreads();
    const float mu = s_mu, rs = s_rs;
    const float4 g  = *(const float4*)(gamma + tid * 4);
    const float4 be = *(const float4*)(beta + tid * 4);
    float4 o4;
    o4.x = g.x * (v.x - mu) * rs + be.x;
    o4.y = g.y * (v.y - mu) * rs + be.y;
    o4.z = g.z * (v.z - mu) * rs + be.z;
    o4.w = g.w * (v.w - mu) * rs + be.w;
    *(float4*)(out + (size_t)row * Ec + tid * 4) = o4;
}

// ---------------- launch ----------------
extern "C" void kernel_launch(void* const* d_in, const int* in_sizes, int n_in,
                              void* d_out, int out_size)
{
    const float* x     = (const float*)d_in[0];
    const float* q_w   = (const float*)d_in[1];
    const float* q_b   = (const float*)d_in[2];
    const float* k_w   = (const float*)d_in[3];
    const float* k_b   = (const float*)d_in[4];
    const float* v_w   = (const float*)d_in[5];
    const float* v_b   = (const float*)d_in[6];
    const float* out_w = (const float*)d_in[7];
    const float* out_b = (const float*)d_in[8];
    const float* proj  = (const float*)d_in[9];
    const float* gamma = (const float*)d_in[10];
    const float* beta  = (const float*)d_in[11];
    float* out = (float*)d_out;

    float *Qp, *Kp, *Vp, *qpp, *kpp, *attnp, *resp;
    cudaGetSymbolAddress((void**)&Qp,    g_Q);
    cudaGetSymbolAddress((void**)&Kp,    g_K);
    cudaGetSymbolAddress((void**)&Vp,    g_V);
    cudaGetSymbolAddress((void**)&qpp,   g_qp);
    cudaGetSymbolAddress((void**)&kpp,   g_kp);
    cudaGetSymbolAddress((void**)&attnp, g_attn);
    cudaGetSymbolAddress((void**)&resp,  g_res);

    const dim3 gg(Ec / 128, (Bc * Sc) / 128);        // (8, 64)
    const dim3 gf(Mc / 128, (Bc * Sc * Hc) / 128);   // (2, 1024)

    sgemm_bias<<<gg, 256>>>(x, q_w, q_b, nullptr, Qp, Bc * Sc, Ec, Ec);
    sgemm_bias<<<gg, 256>>>(x, k_w, k_b, nullptr, Kp, Bc * Sc, Ec, Ec);
    sgemm_bias<<<gg, 256>>>(x, v_w, v_b, nullptr, Vp, Bc * Sc, Ec, Ec);

    feature_kernel<<<gf, 256>>>(Qp, proj, qpp);
    feature_kernel<<<gf, 256>>>(Kp, proj, kpp);

    scan_kernel<<<Bc * Hc * 2, 256>>>(qpp, kpp, Vp, attnp);

    sgemm_bias<<<gg, 256>>>(attnp, out_w, out_b, x, resp, Bc * Sc, Ec, Ec);

    ln_kernel<<<Bc * Sc, 256>>>(resp, gamma, beta, out);
}

// round 10
// speedup vs baseline: 1.0013x; 1.0013x over previous
#include <cuda_runtime.h>
#include <math.h>

#define Bc 4
#define Sc 2048
#define Ec 1024
#define Hc 16
#define Mc 256
#define Dc 64

typedef unsigned long long u64;

// ---------------- packed f32x2 helpers (Blackwell FFMA2) ----------------
__device__ __forceinline__ u64 ffma2(u64 a, u64 b, u64 c) {
    u64 d;
    asm("fma.rn.f32x2 %0, %1, %2, %3;" : "=l"(d) : "l"(a), "l"(b), "l"(c));
    return d;
}
__device__ __forceinline__ u64 pack2(float x, float y) {
    u64 r;
    asm("mov.b64 %0, {%1, %2};" : "=l"(r) : "f"(x), "f"(y));
    return r;
}
__device__ __forceinline__ float2 unpack2(u64 v) {
    float2 r;
    asm("mov.b64 {%0, %1}, %2;" : "=f"(r.x), "=f"(r.y) : "l"(v));
    return r;
}

// ---------------- scratch (device globals; no runtime allocation) ----------------
__device__ float g_Q[Bc*Sc*Ec];
__device__ float g_K[Bc*Sc*Ec];
__device__ float g_V[Bc*Sc*Ec];
__device__ float g_qp[(size_t)Bc*Hc*Sc*Mc];
__device__ float g_kp[(size_t)Bc*Hc*Sc*Mc];
__device__ float g_attn[Bc*Sc*Ec];
__device__ float g_res[Bc*Sc*Ec];

// ---------------- fp32 tiled GEMM (FFMA2 core, reg-staged double buffer) ----------------
// C = A@B + bias (+ add). A:[Mr,K] B:[K,N] bias:[N] add:[Mr,N]|null C:[Mr,N]
// BM=BN=128, BK=16, 256 threads, 8x8 per thread (as 8x4 f32x2 pairs).
__global__ void __launch_bounds__(256)
sgemm_bias(const float* __restrict__ A, const float* __restrict__ B,
           const float* __restrict__ bias, const float* __restrict__ add,
           float* __restrict__ C, int Mr, int N, int K)
{
    __shared__ __align__(16) float As[16][128];
    __shared__ __align__(16) float Bs[16][128];
    const int tid  = threadIdx.x;
    const int tx   = tid & 15;
    const int ty   = tid >> 4;
    const int row0 = blockIdx.y * 128;
    const int col0 = blockIdx.x * 128;

    const int id0 = tid << 1;
    int rA[2], kcA[2], krB[2], ncB[2];
    #pragma unroll
    for (int i = 0; i < 2; i++) {
        const int id = id0 + i;
        rA[i]  = id >> 2;
        kcA[i] = (id & 3) << 2;
        krB[i] = id >> 5;
        ncB[i] = (id & 31) << 2;
    }

    float4 pa[2], pb[2];
    #pragma unroll
    for (int i = 0; i < 2; i++) {
        pa[i] = *(const float4*)(A + (size_t)(row0 + rA[i]) * K + kcA[i]);
        pb[i] = *(const float4*)(B + (size_t)krB[i] * N + col0 + ncB[i]);
    }
    #pragma unroll
    for (int i = 0; i < 2; i++) {
        As[kcA[i] + 0][rA[i]] = pa[i].x;
        As[kcA[i] + 1][rA[i]] = pa[i].y;
        As[kcA[i] + 2][rA[i]] = pa[i].z;
        As[kcA[i] + 3][rA[i]] = pa[i].w;
        *(float4*)(&Bs[krB[i]][ncB[i]]) = pb[i];
    }
    __syncthreads();

    u64 acc[8][4];
    #pragma unroll
    for (int i = 0; i < 8; i++)
        #pragma unroll
        for (int j = 0; j < 4; j++) acc[i][j] = 0ull;

    const int nT = K >> 4;
    for (int t = 0; t < nT; t++) {
        const int k0n = (t + 1) << 4;
        if (k0n < K) {
            #pragma unroll
            for (int i = 0; i < 2; i++) {
                pa[i] = *(const float4*)(A + (size_t)(row0 + rA[i]) * K + k0n + kcA[i]);
                pb[i] = *(const float4*)(B + (size_t)(k0n + krB[i]) * N + col0 + ncB[i]);
            }
        }
        #pragma unroll
        for (int k = 0; k < 16; k++) {
            float4 a0 = *(const float4*)(&As[k][ty * 8]);
            float4 a1 = *(const float4*)(&As[k][ty * 8 + 4]);
            ulonglong2 b0 = *(const ulonglong2*)(&Bs[k][tx * 8]);
            ulonglong2 b1 = *(const ulonglong2*)(&Bs[k][tx * 8 + 4]);
            u64 rb[4] = { b0.x, b0.y, b1.x, b1.y };
            u64 ra[8] = { pack2(a0.x, a0.x), pack2(a0.y, a0.y),
                          pack2(a0.z, a0.z), pack2(a0.w, a0.w),
                          pack2(a1.x, a1.x), pack2(a1.y, a1.y),
                          pack2(a1.z, a1.z), pack2(a1.w, a1.w) };
            #pragma unroll
            for (int i = 0; i < 8; i++)
                #pragma unroll
                for (int j = 0; j < 4; j++)
                    acc[i][j] = ffma2(ra[i], rb[j], acc[i][j]);
        }
        __syncthreads();
        if (k0n < K) {
            #pragma unroll
            for (int i = 0; i < 2; i++) {
                As[kcA[i] + 0][rA[i]] = pa[i].x;
                As[kcA[i] + 1][rA[i]] = pa[i].y;
                As[kcA[i] + 2][rA[i]] = pa[i].z;
                As[kcA[i] + 3][rA[i]] = pa[i].w;
                *(float4*)(&Bs[krB[i]][ncB[i]]) = pb[i];
            }
            __syncthreads();
        }
    }

    #pragma unroll
    for (int i = 0; i < 8; i++) {
        const size_t rbase = (size_t)(row0 + ty * 8 + i) * N;
        const int ci = col0 + tx * 8;
        const float2 v0 = unpack2(acc[i][0]);
        const float2 v1 = unpack2(acc[i][1]);
        const float2 v2 = unpack2(acc[i][2]);
        const float2 v3 = unpack2(acc[i][3]);
        float4 r0, r1;
        r0.x = v0.x + __ldg(bias + ci + 0);
        r0.y = v0.y + __ldg(bias + ci + 1);
        r0.z = v1.x + __ldg(bias + ci + 2);
        r0.w = v1.y + __ldg(bias + ci + 3);
        r1.x = v2.x + __ldg(bias + ci + 4);
        r1.y = v2.y + __ldg(bias + ci + 5);
        r1.z = v3.x + __ldg(bias + ci + 6);
        r1.w = v3.y + __ldg(bias + ci + 7);
        if (add) {
            const float4 a0 = *(const float4*)(add + rbase + ci);
            const float4 a1 = *(const float4*)(add + rbase + ci + 4);
            r0.x += a0.x; r0.y += a0.y; r0.z += a0.z; r0.w += a0.w;
            r1.x += a1.x; r1.y += a1.y; r1.z += a1.z; r1.w += a1.w;
        }
        *(float4*)(C + rbase + ci)     = r0;
        *(float4*)(C + rbase + ci + 4) = r1;
    }
}

// ---------------- feature map (FFMA2) ----------------
__global__ void __launch_bounds__(256)
feature_kernel(const float* __restrict__ A, const float* __restrict__ proj,
               float* __restrict__ out)
{
    __shared__ __align__(16) float As[16][128];
    __shared__ __align__(16) float Bs[16][128];
    __shared__ float s2[128][2];
    const int tid  = threadIdx.x;
    const int tx   = tid & 15;
    const int ty   = tid >> 4;
    const int row0 = blockIdx.y * 128;
    const int col0 = blockIdx.x * 128;

    {
        int r = tid >> 1, half = tid & 1;
        const float* p = A + (size_t)(row0 + r) * Dc + half * 32;
        float s = 0.f;
        #pragma unroll
        for (int i = 0; i < 32; i++) s = fmaf(p[i], p[i], s);
        s2[r][half] = s;
    }

    u64 acc[8][4];
    #pragma unroll
    for (int i = 0; i < 8; i++)
        #pragma unroll
        for (int j = 0; j < 4; j++) acc[i][j] = 0ull;

    for (int k0 = 0; k0 < Dc; k0 += 16) {
        #pragma unroll
        for (int i = 0; i < 2; i++) {
            int id = (tid << 1) + i;
            int r  = id >> 2;
            int kc = (id & 3) << 2;
            const float4 a = *(const float4*)(A + (size_t)(row0 + r) * Dc + k0 + kc);
            As[kc + 0][r] = a.x;
            As[kc + 1][r] = a.y;
            As[kc + 2][r] = a.z;
            As[kc + 3][r] = a.w;
            int kr = id >> 5;
            int nc = (id & 31) << 2;
            Bs[kr][nc + 0] = proj[(size_t)(col0 + nc + 0) * Dc + k0 + kr];
            Bs[kr][nc + 1] = proj[(size_t)(col0 + nc + 1) * Dc + k0 + kr];
            Bs[kr][nc + 2] = proj[(size_t)(col0 + nc + 2) * Dc + k0 + kr];
            Bs[kr][nc + 3] = proj[(size_t)(col0 + nc + 3) * Dc + k0 + kr];
        }
        __syncthreads();
        #pragma unroll
        for (int k = 0; k < 16; k++) {
            float4 a0 = *(const float4*)(&As[k][ty * 8]);
            float4 a1 = *(const float4*)(&As[k][ty * 8 + 4]);
            ulonglong2 b0 = *(const ulonglong2*)(&Bs[k][tx * 8]);
            ulonglong2 b1 = *(const ulonglong2*)(&Bs[k][tx * 8 + 4]);
            u64 rb[4] = { b0.x, b0.y, b1.x, b1.y };
            u64 ra[8] = { pack2(a0.x, a0.x), pack2(a0.y, a0.y),
                          pack2(a0.z, a0.z), pack2(a0.w, a0.w),
                          pack2(a1.x, a1.x), pack2(a1.y, a1.y),
                          pack2(a1.z, a1.z), pack2(a1.w, a1.w) };
            #pragma unroll
            for (int i = 0; i < 8; i++)
                #pragma unroll
                for (int j = 0; j < 4; j++)
                    acc[i][j] = ffma2(ra[i], rb[j], acc[i][j]);
        }
        __syncthreads();
    }

    #pragma unroll
    for (int i = 0; i < 8; i++) {
        const int rr = ty * 8 + i;
        const int r  = row0 + rr;
        const float ss = s2[rr][0] + s2[rr][1];
        const int b = r >> 15;
        const int s = (r >> 4) & (Sc - 1);
        const int h = r & (Hc - 1);
        const size_t obase = ((size_t)(b * Hc + h) * Sc + s) * Mc + col0 + tx * 8;
        const float corr = ss * (1.f / 128.f);
        float vals[8];
        const float2 v0 = unpack2(acc[i][0]);
        const float2 v1 = unpack2(acc[i][1]);
        const float2 v2 = unpack2(acc[i][2]);
        const float2 v3 = unpack2(acc[i][3]);
        vals[0] = v0.x; vals[1] = v0.y; vals[2] = v1.x; vals[3] = v1.y;
        vals[4] = v2.x; vals[5] = v2.y; vals[6] = v3.x; vals[7] = v3.y;
        #pragma unroll
        for (int j = 0; j < 8; j++)
            out[obase + j] = 0.0625f * expf(fmaf(vals[j], 0.125f, -corr));
    }
}

// ---------------- causal linear-attention scan, D split across 2 CTAs ----------------
// CTA = (bh, half). Thread (c=tid>>5, dl=tid&31) owns kv[m in c*32..c*32+31][half*32+dl].
// 128 CTAs -> ~1 per SM (vs 64 before): compute floor halves.
__global__ void __launch_bounds__(256)
scan_kernel(const float* __restrict__ qp, const float* __restrict__ kp,
            const float* __restrict__ V, float* __restrict__ attn)
{
    const int bh   = blockIdx.x >> 1;
    const int half = blockIdx.x & 1;
    const int b    = bh >> 4;
    const int h    = bh & 15;
    const int tid  = threadIdx.x;
    const int c    = tid >> 5;    // 0..7 (m-chunk)
    const int dl   = tid & 31;    // 0..31 (local d)

    __shared__ __align__(16) float q_sh[256];
    __shared__ __align__(16) float k_sh[256];
    __shared__ float v_sh[32];
    __shared__ float ksum_sh[256];
    __shared__ float nred[8][32];
    __shared__ float dred[8];

    u64 kv[16];
    #pragma unroll
    for (int i = 0; i < 16; i++) kv[i] = 0ull;
    ksum_sh[tid] = 0.f;

    const float* qpb = qp + (size_t)bh * Sc * Mc;
    const float* kpb = kp + (size_t)bh * Sc * Mc;
    const float* Vb  = V + ((size_t)b * Sc * Hc + h) * Dc + half * 32;
    float*       ab  = attn + ((size_t)b * Sc * Hc + h) * Dc + half * 32;

    // prefetch step 0
    float qn = qpb[tid];
    float kn = kpb[tid];
    float vn = (tid < 32) ? Vb[tid] : 0.f;

    for (int s = 0; s < Sc; s++) {
        q_sh[tid] = qn;
        k_sh[tid] = kn;
        if (tid < 32) v_sh[tid] = vn;
        __syncthreads();

        // prefetch next step (hidden under compute)
        if (s + 1 < Sc) {
            qn = qpb[(size_t)(s + 1) * Mc + tid];
            kn = kpb[(size_t)(s + 1) * Mc + tid];
            if (tid < 32) vn = Vb[(size_t)(s + 1) * Hc * Dc + tid];
        }

        // ksum update + den partial (thread t owns m = t; warp w covers m in [32w,32w+32))
        float ks = ksum_sh[tid] + k_sh[tid];
        ksum_sh[tid] = ks;
        float dp = q_sh[tid] * ks;
        #pragma unroll
        for (int o = 16; o > 0; o >>= 1) dp += __shfl_down_sync(0xffffffffu, dp, o);
        if (dl == 0) dred[c] = dp;

        // kv update + num partial over this thread's 32 m-values (f32x2)
        const u64 vd2 = pack2(v_sh[dl], v_sh[dl]);
        u64 np0 = 0ull, np1 = 0ull;
        const ulonglong2* k4 = (const ulonglong2*)(k_sh + (c << 5));
        const ulonglong2* q4 = (const ulonglong2*)(q_sh + (c << 5));
        #pragma unroll
        for (int i = 0; i < 8; i++) {
            const ulonglong2 kk = k4[i];
            const ulonglong2 qq = q4[i];
            kv[2*i + 0] = ffma2(kk.x, vd2, kv[2*i + 0]);
            np0 = ffma2(kv[2*i + 0], qq.x, np0);
            kv[2*i + 1] = ffma2(kk.y, vd2, kv[2*i + 1]);
            np1 = ffma2(kv[2*i + 1], qq.y, np1);
        }
        const float2 n0 = unpack2(np0);
        const float2 n1 = unpack2(np1);
        nred[c][dl] = (n0.x + n0.y) + (n1.x + n1.y);
        __syncthreads();

        if (tid < 32) {
            const float num = nred[0][tid] + nred[1][tid] + nred[2][tid] + nred[3][tid]
                            + nred[4][tid] + nred[5][tid] + nred[6][tid] + nred[7][tid];
            const float den = dred[0] + dred[1] + dred[2] + dred[3]
                            + dred[4] + dred[5] + dred[6] + dred[7];
            ab[(size_t)s * Hc * Dc + tid] = num / den;
        }
    }
}

// ---------------- layernorm ----------------
__global__ void __launch_bounds__(256)
ln_kernel(const float* __restrict__ res, const float* __restrict__ gamma,
          const float* __restrict__ beta, float* __restrict__ out)
{
    const int row = blockIdx.x;
    const int tid = threadIdx.x;
    const float4 v = *(const float4*)(res + (size_t)row * Ec + tid * 4);
    float s  = v.x + v.y + v.z + v.w;
    float sq = v.x * v.x + v.y * v.y + v.z * v.z + v.w * v.w;
    #pragma unroll
    for (int o = 16; o > 0; o >>= 1) {
        s  += __shfl_down_sync(0xffffffffu, s,  o);
        sq += __shfl_down_sync(0xffffffffu, sq, o);
    }
    __shared__ float ssh[8], sqsh[8];
    __shared__ float s_mu, s_rs;
    if ((tid & 31) == 0) { ssh[tid >> 5] = s; sqsh[tid >> 5] = sq; }
    __syncthreads();
    if (tid == 0) {
        float S = 0.f, Q = 0.f;
        #pragma unroll
        for (int w = 0; w < 8; w++) { S += ssh[w]; Q += sqsh[w]; }
        const float mu  = S * (1.f / Ec);
        const float var = Q * (1.f / Ec) - mu * mu;
        s_mu = mu;
        s_rs = rsqrtf(var + 1e-6f);
    }
    __syncthreads();
    const float mu = s_mu, rs = s_rs;
    const float4 g  = *(const float4*)(gamma + tid * 4);
    const float4 be = *(const float4*)(beta + tid * 4);
    float4 o4;
    o4.x = g.x * (v.x - mu) * rs + be.x;
    o4.y = g.y * (v.y - mu) * rs + be.y;
    o4.z = g.z * (v.z - mu) * rs + be.z;
    o4.w = g.w * (v.w - mu) * rs + be.w;
    *(float4*)(out + (size_t)row * Ec + tid * 4) = o4;
}

// ---------------- launch ----------------
extern "C" void kernel_launch(void* const* d_in, const int* in_sizes, int n_in,
                              void* d_out, int out_size)
{
    const float* x     = (const float*)d_in[0];
    const float* q_w   = (const float*)d_in[1];
    const float* q_b   = (const float*)d_in[2];
    const float* k_w   = (const float*)d_in[3];
    const float* k_b   = (const float*)d_in[4];
    const float* v_w   = (const float*)d_in[5];
    const float* v_b   = (const float*)d_in[6];
    const float* out_w = (const float*)d_in[7];
    const float* out_b = (const float*)d_in[8];
    const float* proj  = (const float*)d_in[9];
    const float* gamma = (const float*)d_in[10];
    const float* beta  = (const float*)d_in[11];
    float* out = (float*)d_out;

    float *Qp, *Kp, *Vp, *qpp, *kpp, *attnp, *resp;
    cudaGetSymbolAddress((void**)&Qp,    g_Q);
    cudaGetSymbolAddress((void**)&Kp,    g_K);
    cudaGetSymbolAddress((void**)&Vp,    g_V);
    cudaGetSymbolAddress((void**)&qpp,   g_qp);
    cudaGetSymbolAddress((void**)&kpp,   g_kp);
    cudaGetSymbolAddress((void**)&attnp, g_attn);
    cudaGetSymbolAddress((void**)&resp,  g_res);

    const dim3 gg(Ec / 128, (Bc * Sc) / 128);        // (8, 64)
    const dim3 gf(Mc / 128, (Bc * Sc * Hc) / 128);   // (2, 1024)

    sgemm_bias<<<gg, 256>>>(x, q_w, q_b, nullptr, Qp, Bc * Sc, Ec, Ec);
    sgemm_bias<<<gg, 256>>>(x, k_w, k_b, nullptr, Kp, Bc * Sc, Ec, Ec);
    sgemm_bias<<<gg, 256>>>(x, v_w, v_b, nullptr, Vp, Bc * Sc, Ec, Ec);

    feature_kernel<<<gf, 256>>>(Qp, proj, qpp);
    feature_kernel<<<gf, 256>>>(Kp, proj, kpp);

    scan_kernel<<<Bc * Hc * 2, 256>>>(qpp, kpp, Vp, attnp);

    sgemm_bias<<<gg, 256>>>(attnp, out_w, out_b, x, resp, Bc * Sc, Ec, Ec);

    ln_kernel<<<Bc * Sc, 256>>>(resp, gamma, beta, out);
}

// round 12
// speedup vs baseline: 1.5703x; 1.5682x over previous
#include <cuda_runtime.h>
#include <cuda_bf16.h>
#include <math.h>
#include <stdint.h>

#define Bc 4
#define Sc 2048
#define Ec 1024
#define Hc 16
#define Mc 256
#define Dc 64
#define GK 1024

typedef unsigned long long u64;

// ---------------- packed f32x2 helpers (used by scan; correct under any lowering) ----
__device__ __forceinline__ u64 ffma2(u64 a, u64 b, u64 c) {
    u64 d;
    asm("fma.rn.f32x2 %0, %1, %2, %3;" : "=l"(d) : "l"(a), "l"(b), "l"(c));
    return d;
}
__device__ __forceinline__ u64 pack2(float x, float y) {
    u64 r;
    asm("mov.b64 %0, {%1, %2};" : "=l"(r) : "f"(x), "f"(y));
    return r;
}
__device__ __forceinline__ float2 unpack2(u64 v) {
    float2 r;
    asm("mov.b64 {%0, %1}, %2;" : "=f"(r.x), "=f"(r.y) : "l"(v));
    return r;
}

__device__ __forceinline__ uint32_t smem_u32(const void* p) {
    uint32_t a;
    asm("{ .reg .u64 t; cvta.to.shared.u64 t, %1; cvt.u32.u64 %0, t; }" : "=r"(a) : "l"(p));
    return a;
}

// bf16 tensor-core mma (sm_80+)
__device__ __forceinline__ void mma_bf16(float* c, const uint32_t* a, const uint32_t* b) {
    asm volatile("mma.sync.aligned.m16n8k16.row.col.f32.bf16.bf16.f32 "
        "{%0,%1,%2,%3}, {%4,%5,%6,%7}, {%8,%9}, {%0,%1,%2,%3};"
        : "+f"(c[0]), "+f"(c[1]), "+f"(c[2]), "+f"(c[3])
        : "r"(a[0]), "r"(a[1]), "r"(a[2]), "r"(a[3]), "r"(b[0]), "r"(b[1]));
}

#define LDSM4(r0, r1, r2, r3, addr) \
    asm volatile("ldmatrix.sync.aligned.m8n8.x4.shared.b16 {%0,%1,%2,%3}, [%4];" \
        : "=r"(r0), "=r"(r1), "=r"(r2), "=r"(r3) : "r"(addr))

// ---------------- scratch (device globals; no runtime allocation) ----------------
__device__ float g_Q[Bc*Sc*Ec];
__device__ float g_K[Bc*Sc*Ec];
__device__ float g_V[Bc*Sc*Ec];
__device__ float g_qp[(size_t)Bc*Hc*Sc*Mc];
__device__ float g_kp[(size_t)Bc*Hc*Sc*Mc];
__device__ float g_attn[Bc*Sc*Ec];
__device__ float g_res[Bc*Sc*Ec];
__device__ __nv_bfloat16 g_xh[Bc*Sc*Ec];
__device__ __nv_bfloat16 g_xl[Bc*Sc*Ec];
__device__ __nv_bfloat16 g_ah[Bc*Sc*Ec];
__device__ __nv_bfloat16 g_al[Bc*Sc*Ec];
__device__ __nv_bfloat16 g_wth[4*Ec*Ec];
__device__ __nv_bfloat16 g_wtl[4*Ec*Ec];
__device__ __nv_bfloat16 g_ph[Mc*Dc];
__device__ __nv_bfloat16 g_pl[Mc*Dc];

// ---------------- fp32 -> bf16 hi/lo split (elementwise) ----------------
__global__ void __launch_bounds__(256)
split_kernel(const float* __restrict__ in, __nv_bfloat16* __restrict__ hi,
             __nv_bfloat16* __restrict__ lo)
{
    const size_t i = ((size_t)blockIdx.x * 256 + threadIdx.x) * 4;
    const float4 v = *(const float4*)(in + i);
    __nv_bfloat16 h[4], l[4];
    h[0] = __float2bfloat16(v.x); l[0] = __float2bfloat16(v.x - __bfloat162float(h[0]));
    h[1] = __float2bfloat16(v.y); l[1] = __float2bfloat16(v.y - __bfloat162float(h[1]));
    h[2] = __float2bfloat16(v.z); l[2] = __float2bfloat16(v.z - __bfloat162float(h[2]));
    h[3] = __float2bfloat16(v.w); l[3] = __float2bfloat16(v.w - __bfloat162float(h[3]));
    *(uint2*)(hi + i) = *(uint2*)h;
    *(uint2*)(lo + i) = *(uint2*)l;
}

// ---------------- weight transpose + split: W[K,N] -> hiT/loT [N,K] ----------------
__global__ void __launch_bounds__(256)
wsplit_t(const float* __restrict__ W, __nv_bfloat16* __restrict__ hiT,
         __nv_bfloat16* __restrict__ loT)
{
    __shared__ float tile[32][33];
    const int n0 = blockIdx.x * 32;
    const int k0 = blockIdx.y * 32;
    const int tx = threadIdx.x & 31;
    const int ty = threadIdx.x >> 5;
    #pragma unroll
    for (int r = ty; r < 32; r += 8)
        tile[r][tx] = W[(size_t)(k0 + r) * Ec + n0 + tx];
    __syncthreads();
    #pragma unroll
    for (int r = ty; r < 32; r += 8) {
        const float v = tile[tx][r];
        const __nv_bfloat16 h = __float2bfloat16(v);
        const __nv_bfloat16 l = __float2bfloat16(v - __bfloat162float(h));
        const size_t o = (size_t)(n0 + r) * Ec + k0 + tx;
        hiT[o] = h;
        loT[o] = l;
    }
}

// ---------------- bf16-split tensor-core GEMM (R7, measured) ----------------
#define STAGE_BYTES 32768

__global__ void __launch_bounds__(256)
bgemm_mma(const __nv_bfloat16* __restrict__ Ah, const __nv_bfloat16* __restrict__ Al,
          const __nv_bfloat16* __restrict__ BhT, const __nv_bfloat16* __restrict__ BlT,
          const float* __restrict__ bias, const float* __restrict__ add,
          float* __restrict__ C)
{
    extern __shared__ __align__(16) char smem[];
    const int tid  = threadIdx.x;
    const int lane = tid & 31;
    const int wid  = tid >> 5;
    const int wm   = wid & 1;
    const int wn   = wid >> 1;
    const int gid  = lane >> 2;
    const int tig  = lane & 3;
    const int row0 = blockIdx.y * 128;
    const int col0 = blockIdx.x * 128;
    const uint32_t sb = smem_u32(smem);

    const int matq   = lane >> 3;
    const int rA_off = ((matq & 1) << 3) | (lane & 7);
    const int kcA    = matq >> 1;
    const int rB_off = ((matq >> 1) << 3) | (lane & 7);
    const int kcB    = matq & 1;
    const int cA     = (rA_off >> 1) & 3;
    const int cB     = (rB_off >> 1) & 3;

    const __nv_bfloat16* gsrc[4] = {
        Ah  + (size_t)row0 * GK, Al  + (size_t)row0 * GK,
        BhT + (size_t)col0 * GK, BlT + (size_t)col0 * GK
    };

    const int r0s = (tid * 2) >> 2,     kc0 = (tid * 2) & 3;
    const int r1s = (tid * 2 + 1) >> 2, kc1 = (tid * 2 + 1) & 3;
    const int c0s = ((r0s >> 1) & 3) ^ kc0;
    const int c1s = ((r1s >> 1) & 3) ^ kc1;

    #define LOAD_STAGE(s, k0) do { \
        _Pragma("unroll") \
        for (int tI = 0; tI < 4; tI++) { \
            uint32_t d0 = sb + (s)*STAGE_BYTES + tI*8192 + r0s*64 + (c0s << 4); \
            uint32_t d1 = sb + (s)*STAGE_BYTES + tI*8192 + r1s*64 + (c1s << 4); \
            const __nv_bfloat16* s0 = gsrc[tI] + (size_t)r0s * GK + (k0) + kc0*8; \
            const __nv_bfloat16* s1 = gsrc[tI] + (size_t)r1s * GK + (k0) + kc1*8; \
            asm volatile("cp.async.cg.shared.global [%0], [%1], 16;" :: "r"(d0), "l"(s0)); \
            asm volatile("cp.async.cg.shared.global [%0], [%1], 16;" :: "r"(d1), "l"(s1)); \
        } \
    } while (0)

    float acc[4][4][4];
    #pragma unroll
    for (int i = 0; i < 4; i++)
        #pragma unroll
        for (int j = 0; j < 4; j++)
            #pragma unroll
            for (int q = 0; q < 4; q++) acc[i][j][q] = 0.f;

    LOAD_STAGE(0, 0);
    asm volatile("cp.async.commit_group;" ::: "memory");
    LOAD_STAGE(1, 32);
    asm volatile("cp.async.commit_group;" ::: "memory");

    const int NT = GK / 32;
    #pragma unroll 1
    for (int t = 0; t < NT; t++) {
        asm volatile("cp.async.wait_group 1;" ::: "memory");
        __syncthreads();
        if (t + 2 < NT) LOAD_STAGE((t + 2) % 3, (t + 2) * 32);
        asm volatile("cp.async.commit_group;" ::: "memory");

        const uint32_t sbS = sb + (t % 3) * STAGE_BYTES;
        #pragma unroll
        for (int ks = 0; ks < 32; ks += 16) {
            const int kb = ks >> 3;
            uint32_t bh[4][2], bl[4][2];
            #pragma unroll
            for (int p = 0; p < 2; p++) {
                const uint32_t baddr = sbS + 2*8192 +
                    (uint32_t)(wn * 32 + p * 16 + rB_off) * 64 + ((cB ^ (kb + kcB)) << 4);
                LDSM4(bh[2*p][0], bh[2*p][1], bh[2*p+1][0], bh[2*p+1][1], baddr);
                LDSM4(bl[2*p][0], bl[2*p][1], bl[2*p+1][0], bl[2*p+1][1], baddr + 8192);
            }
            #pragma unroll
            for (int mf = 0; mf < 4; mf++) {
                uint32_t ah[4], al[4];
                const uint32_t aaddr = sbS +
                    (uint32_t)(wm * 64 + mf * 16 + rA_off) * 64 + ((cA ^ (kb + kcA)) << 4);
                LDSM4(ah[0], ah[1], ah[2], ah[3], aaddr);
                LDSM4(al[0], al[1], al[2], al[3], aaddr + 8192);
                #pragma unroll
                for (int nf = 0; nf < 4; nf++) mma_bf16(acc[mf][nf], ah, bh[nf]);
                #pragma unroll
                for (int nf = 0; nf < 4; nf++) mma_bf16(acc[mf][nf], ah, bl[nf]);
                #pragma unroll
                for (int nf = 0; nf < 4; nf++) mma_bf16(acc[mf][nf], al, bh[nf]);
            }
        }
    }

    #pragma unroll
    for (int mf = 0; mf < 4; mf++) {
        const int row = row0 + wm * 64 + mf * 16 + gid;
        #pragma unroll
        for (int nf = 0; nf < 4; nf++) {
            const int col = col0 + wn * 32 + nf * 8 + tig * 2;
            const float b0 = __ldg(bias + col);
            const float b1 = __ldg(bias + col + 1);
            float2 v0, v1;
            v0.x = acc[mf][nf][0] + b0; v0.y = acc[mf][nf][1] + b1;
            v1.x = acc[mf][nf][2] + b0; v1.y = acc[mf][nf][3] + b1;
            const size_t o0 = (size_t)row * Ec + col;
            const size_t o1 = (size_t)(row + 8) * Ec + col;
            if (add) {
                const float2 a0 = *(const float2*)(add + o0);
                const float2 a1 = *(const float2*)(add + o1);
                v0.x += a0.x; v0.y += a0.y;
                v1.x += a1.x; v1.y += a1.y;
            }
            *(float2*)(C + o0) = v0;
            *(float2*)(C + o1) = v1;
        }
    }
}

// ---------------- feature map on tensor cores ----------------
// out[b,h,s,m] = (1/16) exp(dot(A_row, proj_m)/8 - |A_row|^2/128), A rows = (b,s,h) flat.
// A via (Ahh,All) K-major bf16 splits; proj via (Ph,Pl) [M,D] K-major bf16 splits.
// CTA 128 rows x 128 m-cols, K=64 (2 k-tiles, both preloaded). Same warp layout as bgemm.
__global__ void __launch_bounds__(256)
feature_mma(const __nv_bfloat16* __restrict__ Ahh, const __nv_bfloat16* __restrict__ All,
            const __nv_bfloat16* __restrict__ Ph, const __nv_bfloat16* __restrict__ Pl,
            const float* __restrict__ Afp, float* __restrict__ out)
{
    extern __shared__ __align__(16) char smem[];
    __shared__ float s2[128][2];
    const int tid  = threadIdx.x;
    const int lane = tid & 31;
    const int wid  = tid >> 5;
    const int wm   = wid & 1;
    const int wn   = wid >> 1;
    const int gid  = lane >> 2;
    const int tig  = lane & 3;
    const int row0 = blockIdx.y * 128;
    const int col0 = blockIdx.x * 128;
    const uint32_t sb = smem_u32(smem);

    const int matq   = lane >> 3;
    const int rA_off = ((matq & 1) << 3) | (lane & 7);
    const int kcA    = matq >> 1;
    const int rB_off = ((matq >> 1) << 3) | (lane & 7);
    const int kcB    = matq & 1;
    const int cA     = (rA_off >> 1) & 3;
    const int cB     = (rB_off >> 1) & 3;

    const __nv_bfloat16* gsrc[4] = {
        Ahh + (size_t)row0 * Dc, All + (size_t)row0 * Dc,
        Ph  + (size_t)col0 * Dc, Pl  + (size_t)col0 * Dc
    };

    const int r0s = (tid * 2) >> 2,     kc0 = (tid * 2) & 3;
    const int r1s = (tid * 2 + 1) >> 2, kc1 = (tid * 2 + 1) & 3;
    const int c0s = ((r0s >> 1) & 3) ^ kc0;
    const int c1s = ((r1s >> 1) & 3) ^ kc1;

    #define LOAD_STAGE_F(s, k0) do { \
        _Pragma("unroll") \
        for (int tI = 0; tI < 4; tI++) { \
            uint32_t d0 = sb + (s)*STAGE_BYTES + tI*8192 + r0s*64 + (c0s << 4); \
            uint32_t d1 = sb + (s)*STAGE_BYTES + tI*8192 + r1s*64 + (c1s << 4); \
            const __nv_bfloat16* s0 = gsrc[tI] + (size_t)r0s * Dc + (k0) + kc0*8; \
            const __nv_bfloat16* s1 = gsrc[tI] + (size_t)r1s * Dc + (k0) + kc1*8; \
            asm volatile("cp.async.cg.shared.global [%0], [%1], 16;" :: "r"(d0), "l"(s0)); \
            asm volatile("cp.async.cg.shared.global [%0], [%1], 16;" :: "r"(d1), "l"(s1)); \
        } \
    } while (0)

    LOAD_STAGE_F(0, 0);
    LOAD_STAGE_F(1, 32);
    asm volatile("cp.async.commit_group;" ::: "memory");

    // per-row |A|^2 in fp32 (2 threads/row, 32 elems each) while loads fly
    {
        int r = tid >> 1, half = tid & 1;
        const float* p = Afp + (size_t)(row0 + r) * Dc + half * 32;
        float s = 0.f;
        #pragma unroll
        for (int i = 0; i < 32; i++) s = fmaf(p[i], p[i], s);
        s2[r][half] = s;
    }

    float acc[4][4][4];
    #pragma unroll
    for (int i = 0; i < 4; i++)
        #pragma unroll
        for (int j = 0; j < 4; j++)
            #pragma unroll
            for (int q = 0; q < 4; q++) acc[i][j][q] = 0.f;

    asm volatile("cp.async.wait_group 0;" ::: "memory");
    __syncthreads();

    #pragma unroll
    for (int t = 0; t < 2; t++) {
        const uint32_t sbS = sb + t * STAGE_BYTES;
        #pragma unroll
        for (int ks = 0; ks < 32; ks += 16) {
            const int kb = ks >> 3;
            uint32_t bh[4][2], bl[4][2];
            #pragma unroll
            for (int p = 0; p < 2; p++) {
                const uint32_t baddr = sbS + 2*8192 +
                    (uint32_t)(wn * 32 + p * 16 + rB_off) * 64 + ((cB ^ (kb + kcB)) << 4);
                LDSM4(bh[2*p][0], bh[2*p][1], bh[2*p+1][0], bh[2*p+1][1], baddr);
                LDSM4(bl[2*p][0], bl[2*p][1], bl[2*p+1][0], bl[2*p+1][1], baddr + 8192);
            }
            #pragma unroll
            for (int mf = 0; mf < 4; mf++) {
                uint32_t ah[4], al[4];
                const uint32_t aaddr = sbS +
                    (uint32_t)(wm * 64 + mf * 16 + rA_off) * 64 + ((cA ^ (kb + kcA)) << 4);
                LDSM4(ah[0], ah[1], ah[2], ah[3], aaddr);
                LDSM4(al[0], al[1], al[2], al[3], aaddr + 8192);
                #pragma unroll
                for (int nf = 0; nf < 4; nf++) mma_bf16(acc[mf][nf], ah, bh[nf]);
                #pragma unroll
                for (int nf = 0; nf < 4; nf++) mma_bf16(acc[mf][nf], ah, bl[nf]);
                #pragma unroll
                for (int nf = 0; nf < 4; nf++) mma_bf16(acc[mf][nf], al, bh[nf]);
            }
        }
    }

    // epilogue: exp + scatter to [b,h,s,m]
    #pragma unroll
    for (int mf = 0; mf < 4; mf++) {
        const int rbase = wm * 64 + mf * 16 + gid;
        #pragma unroll
        for (int rr = 0; rr < 2; rr++) {
            const int rl  = rbase + rr * 8;            // local row
            const int row = row0 + rl;                 // flattened (b,s,h)
            const int b = row >> 15;
            const int s = (row >> 4) & (Sc - 1);
            const int h = row & (Hc - 1);
            const size_t obase = ((size_t)(b * Hc + h) * Sc + s) * Mc;
            const float corr = (s2[rl][0] + s2[rl][1]) * (1.f / 128.f);
            #pragma unroll
            for (int nf = 0; nf < 4; nf++) {
                const int col = col0 + wn * 32 + nf * 8 + tig * 2;
                float2 o;
                o.x = 0.0625f * expf(fmaf(acc[mf][nf][rr*2+0], 0.125f, -corr));
                o.y = 0.0625f * expf(fmaf(acc[mf][nf][rr*2+1], 0.125f, -corr));
                *(float2*)(out + obase + col) = o;
            }
        }
    }
}

// ---------------- causal linear-attention scan, D split across 2 CTAs (R9) ----------------
__global__ void __launch_bounds__(256)
scan_kernel(const float* __restrict__ qp, const float* __restrict__ kp,
            const float* __restrict__ V, float* __restrict__ attn)
{
    const int bh   = blockIdx.x >> 1;
    const int half = blockIdx.x & 1;
    const int b    = bh >> 4;
    const int h    = bh & 15;
    const int tid  = threadIdx.x;
    const int c    = tid >> 5;
    const int dl   = tid & 31;

    __shared__ __align__(16) float q_sh[256];
    __shared__ __align__(16) float k_sh[256];
    __shared__ float v_sh[32];
    __shared__ float ksum_sh[256];
    __shared__ float nred[8][32];
    __shared__ float dred[8];

    u64 kv[16];
    #pragma unroll
    for (int i = 0; i < 16; i++) kv[i] = 0ull;
    ksum_sh[tid] = 0.f;

    const float* qpb = qp + (size_t)bh * Sc * Mc;
    const float* kpb = kp + (size_t)bh * Sc * Mc;
    const float* Vb  = V + ((size_t)b * Sc * Hc + h) * Dc + half * 32;
    float*       ab  = attn + ((size_t)b * Sc * Hc + h) * Dc + half * 32;

    float qn = qpb[tid];
    float kn = kpb[tid];
    float vn = (tid < 32) ? Vb[tid] : 0.f;

    for (int s = 0; s < Sc; s++) {
        q_sh[tid] = qn;
        k_sh[tid] = kn;
        if (tid < 32) v_sh[tid] = vn;
        __syncthreads();

        if (s + 1 < Sc) {
            qn = qpb[(size_t)(s + 1) * Mc + tid];
            kn = kpb[(size_t)(s + 1) * Mc + tid];
            if (tid < 32) vn = Vb[(size_t)(s + 1) * Hc * Dc + tid];
        }

        float ks = ksum_sh[tid] + k_sh[tid];
        ksum_sh[tid] = ks;
        float dp = q_sh[tid] * ks;
        #pragma unroll
        for (int o = 16; o > 0; o >>= 1) dp += __shfl_down_sync(0xffffffffu, dp, o);
        if (dl == 0) dred[c] = dp;

        const u64 vd2 = pack2(v_sh[dl], v_sh[dl]);
        u64 np0 = 0ull, np1 = 0ull;
        const ulonglong2* k4 = (const ulonglong2*)(k_sh + (c << 5));
        const ulonglong2* q4 = (const ulonglong2*)(q_sh + (c << 5));
        #pragma unroll
        for (int i = 0; i < 8; i++) {
            const ulonglong2 kk = k4[i];
            const ulonglong2 qq = q4[i];
            kv[2*i + 0] = ffma2(kk.x, vd2, kv[2*i + 0]);
            np0 = ffma2(kv[2*i + 0], qq.x, np0);
            kv[2*i + 1] = ffma2(kk.y, vd2, kv[2*i + 1]);
            np1 = ffma2(kv[2*i + 1], qq.y, np1);
        }
        const float2 n0 = unpack2(np0);
        const float2 n1 = unpack2(np1);
        nred[c][dl] = (n0.x + n0.y) + (n1.x + n1.y);
        __syncthreads();

        if (tid < 32) {
            const float num = nred[0][tid] + nred[1][tid] + nred[2][tid] + nred[3][tid]
                            + nred[4][tid] + nred[5][tid] + nred[6][tid] + nred[7][tid];
            const float den = dred[0] + dred[1] + dred[2] + dred[3]
                            + dred[4] + dred[5] + dred[6] + dred[7];
            ab[(size_t)s * Hc * Dc + tid] = num / den;
        }
    }
}

// ---------------- layernorm ----------------
__global__ void __launch_bounds__(256)
ln_kernel(const float* __restrict__ res, const float* __restrict__ gamma,
          const float* __restrict__ beta, float* __restrict__ out)
{
    const int row = blockIdx.x;
    const int tid = threadIdx.x;
    const float4 v = *(const float4*)(res + (size_t)row * Ec + tid * 4);
    float s  = v.x + v.y + v.z + v.w;
    float sq = v.x * v.x + v.y * v.y + v.z * v.z + v.w * v.w;
    #pragma unroll
    for (int o = 16; o > 0; o >>= 1) {
        s  += __shfl_down_sync(0xffffffffu, s,  o);
        sq += __shfl_down_sync(0xffffffffu, sq, o);
    }
    __shared__ float ssh[8], sqsh[8];
    __shared__ float s_mu, s_rs;
    if ((tid & 31) == 0) { ssh[tid >> 5] = s; sqsh[tid >> 5] = sq; }
    __syncthreads();
    if (tid == 0) {
        float S = 0.f, Q = 0.f;
        #pragma unroll
        for (int w = 0; w < 8; w++) { S += ssh[w]; Q += sqsh[w]; }
        const float mu  = S * (1.f / Ec);
        const float var = Q * (1.f / Ec) - mu * mu;
        s_mu = mu;
        s_rs = rsqrtf(var + 1e-6f);
    }
    __syncthreads();
    const float mu = s_mu, rs = s_rs;
    const float4 g  = *(const float4*)(gamma + tid * 4);
    const float4 be = *(const float4*)(beta + tid * 4);
    float4 o4;
    o4.x = g.x * (v.x - mu) * rs + be.x;
    o4.y = g.y * (v.y - mu) * rs + be.y;
    o4.z = g.z * (v.z - mu) * rs + be.z;
    o4.w = g.w * (v.w - mu) * rs + be.w;
    *(float4*)(out + (size_t)row * Ec + tid * 4) = o4;
}

// ---------------- launch ----------------
extern "C" void kernel_launch(void* const* d_in, const int* in_sizes, int n_in,
                              void* d_out, int out_size)
{
    const float* x     = (const float*)d_in[0];
    const float* q_w   = (const float*)d_in[1];
    const float* q_b   = (const float*)d_in[2];
    const float* k_w   = (const float*)d_in[3];
    const float* k_b   = (const float*)d_in[4];
    const float* v_w   = (const float*)d_in[5];
    const float* v_b   = (const float*)d_in[6];
    const float* out_w = (const float*)d_in[7];
    const float* out_b = (const float*)d_in[8];
    const float* proj  = (const float*)d_in[9];
    const float* gamma = (const float*)d_in[10];
    const float* beta  = (const float*)d_in[11];
    float* out = (float*)d_out;

    float *Qp, *Kp, *Vp, *qpp, *kpp, *attnp, *resp;
    __nv_bfloat16 *xh, *xl, *ah, *al, *wth, *wtl, *ph, *pl;
    cudaGetSymbolAddress((void**)&Qp,    g_Q);
    cudaGetSymbolAddress((void**)&Kp,    g_K);
    cudaGetSymbolAddress((void**)&Vp,    g_V);
    cudaGetSymbolAddress((void**)&qpp,   g_qp);
    cudaGetSymbolAddress((void**)&kpp,   g_kp);
    cudaGetSymbolAddress((void**)&attnp, g_attn);
    cudaGetSymbolAddress((void**)&resp,  g_res);
    cudaGetSymbolAddress((void**)&xh,    g_xh);
    cudaGetSymbolAddress((void**)&xl,    g_xl);
    cudaGetSymbolAddress((void**)&ah,    g_ah);
    cudaGetSymbolAddress((void**)&al,    g_al);
    cudaGetSymbolAddress((void**)&wth,   g_wth);
    cudaGetSymbolAddress((void**)&wtl,   g_wtl);
    cudaGetSymbolAddress((void**)&ph,    g_ph);
    cudaGetSymbolAddress((void**)&pl,    g_pl);

    cudaFuncSetAttribute(bgemm_mma,   cudaFuncAttributeMaxDynamicSharedMemorySize, 98304);
    cudaFuncSetAttribute(feature_mma, cudaFuncAttributeMaxDynamicSharedMemorySize, 65536);

    const int NE = Bc * Sc * Ec;                 // 8388608
    const dim3 gw(32, 32);
    const dim3 gb(Ec / 128, (Bc * Sc) / 128);    // (8, 64)
    const dim3 gf(Mc / 128, (Bc * Sc * Hc) / 128);  // (2, 1024)

    split_kernel<<<NE / 1024, 256>>>(x, xh, xl);
    wsplit_t<<<gw, 256>>>(q_w,   wth + 0 * Ec * Ec, wtl + 0 * Ec * Ec);
    wsplit_t<<<gw, 256>>>(k_w,   wth + 1 * Ec * Ec, wtl + 1 * Ec * Ec);
    wsplit_t<<<gw, 256>>>(v_w,   wth + 2 * Ec * Ec, wtl + 2 * Ec * Ec);
    wsplit_t<<<gw, 256>>>(out_w, wth + 3 * Ec * Ec, wtl + 3 * Ec * Ec);
    split_kernel<<<(Mc * Dc) / 1024, 256>>>(proj, ph, pl);

    bgemm_mma<<<gb, 256, 98304>>>(xh, xl, wth + 0 * Ec * Ec, wtl + 0 * Ec * Ec, q_b, nullptr, Qp);
    bgemm_mma<<<gb, 256, 98304>>>(xh, xl, wth + 1 * Ec * Ec, wtl + 1 * Ec * Ec, k_b, nullptr, Kp);
    bgemm_mma<<<gb, 256, 98304>>>(xh, xl, wth + 2 * Ec * Ec, wtl + 2 * Ec * Ec, v_b, nullptr, Vp);

    // feature maps on tensor cores (reuse xh/xl as Q/K split scratch; stream-ordered)
    split_kernel<<<NE / 1024, 256>>>(Qp, xh, xl);
    feature_mma<<<gf, 256, 65536>>>(xh, xl, ph, pl, Qp, qpp);
    split_kernel<<<NE / 1024, 256>>>(Kp, xh, xl);
    feature_mma<<<gf, 256, 65536>>>(xh, xl, ph, pl, Kp, kpp);

    scan_kernel<<<Bc * Hc * 2, 256>>>(qpp, kpp, Vp, attnp);

    split_kernel<<<NE / 1024, 256>>>(attnp, ah, al);
    bgemm_mma<<<gb, 256, 98304>>>(ah, al, wth + 3 * Ec * Ec, wtl + 3 * Ec * Ec, out_b, x, resp);

    ln_kernel<<<Bc * Sc, 256>>>(resp, gamma, beta, out);
}